// round 13
// baseline (speedup 1.0000x reference)
#include <cuda_runtime.h>
#include <cstdint>

// Problem constants
#define BATCH 16
#define CH    256
#define HH    64
#define WW    64
#define TROWS 66                 // 64 data rows + top/bottom zero rows
#define ROWF  68                 // smem row stride (floats); data at cols 0..63
#define NBUF  2
#define BUFF  (TROWS * ROWF)     // 4488 floats per buffer
#define BUFB  (BUFF * 4)         // 17952 bytes per buffer

// Split schedule: co0->16, co1->8, co2->4, co3->2, co4->2 chunks, rest->1.
#define NSPLIT 32
#define GRID_X (NSPLIT + 251)    // 283 schedule entries

// ---------------------------------------------------------------------------
// Scratch (device globals — no runtime allocation allowed)
// ---------------------------------------------------------------------------
__device__ int   g_cin  [CH * CH];
__device__ float g_w    [CH * CH * 12];
__device__ int   g_count[CH];
__device__ float g_part [NSPLIT * BATCH * HH * WW];   // 8 MB partials
__device__ int   g_cnt  [5 * BATCH];                  // per-(co,b) arrival counters

// ---------------------------------------------------------------------------
// cp.async helpers
// ---------------------------------------------------------------------------
__device__ __forceinline__ void cp_async16(uint32_t saddr, const float* gptr, int src_size) {
    asm volatile("cp.async.ca.shared.global [%0], [%1], 16, %2;\n"
                 :: "r"(saddr), "l"(gptr), "r"(src_size));
}
__device__ __forceinline__ void cp_commit() {
    asm volatile("cp.async.commit_group;\n" ::);
}
template <int N> __device__ __forceinline__ void cp_wait() {
    asm volatile("cp.async.wait_group %0;\n" :: "n"(N));
}

// ---------------------------------------------------------------------------
// K1: fused cumprod + compaction.  Block = cout (256), thread = cin (256).
// Each thread computes scale = prod_{j=1..co} relu(weight[j][cin]) serially
// in registers; a uniform early-exit fires once the whole column is zero
// (deep blocks quit after ~16 rows).  Then deterministic ballot/popc
// compaction + scale-folded 3x3 weight pack.  Block 0 also re-zeroes the
// per-(co,b) arrival counters (fresh state every graph replay).
// ---------------------------------------------------------------------------
__global__ void prep_kernel(const float* __restrict__ weight,
                            const float* __restrict__ conv_w) {
    int co  = blockIdx.x;
    int cin = threadIdx.x;

    if (co == 0 && cin < 5 * BATCH) g_cnt[cin] = 0;

    float sc = 1.0f;
    for (int j = 1; j <= co; ++j) {
        sc *= fmaxf(weight[j * CH + cin], 0.0f);
        if ((j & 7) == 0) {
            if (__syncthreads_count(sc != 0.0f) == 0) break;   // uniform exit
        }
    }

    bool active = (sc != 0.0f);
    unsigned mask = __ballot_sync(0xffffffffu, active);
    int lane = cin & 31, warp = cin >> 5;
    __shared__ int wcnt[8];
    if (lane == 0) wcnt[warp] = __popc(mask);
    __syncthreads();
    int base = 0;
    #pragma unroll
    for (int i = 0; i < 8; i++)
        if (i < warp) base += wcnt[i];
    if (active) {
        int slot = base + __popc(mask & ((1u << lane) - 1u));
        g_cin[co * CH + slot] = cin;
        const float* ws = conv_w + (size_t)(co * CH + cin) * 9;
        float*       wd = g_w    + (size_t)(co * CH + slot) * 12;
        #pragma unroll
        for (int k = 0; k < 9; k++) wd[k] = ws[k] * sc;
        wd[9] = 0.0f; wd[10] = 0.0f; wd[11] = 0.0f;
    }
    if (cin == 0) {
        int t = 0;
        #pragma unroll
        for (int i = 0; i < 8; i++) t += wcnt[i];
        g_count[co] = t;
    }
}

// ---------------------------------------------------------------------------
// K2: whole-plane 3x3 conv over a chunk of the compacted channel list, with
// an embedded "last block reduces" epilogue for split couts (no separate
// reduce kernel, no spin, deadlock-free: the reducer is always a producer).
// grid = (283 entries, 16 batch), 256 threads, 4x4 micro-tile per thread,
// 2-buffer cp.async ring, one aligned LDS.128 + 2 shuffles per row.
// ---------------------------------------------------------------------------
__global__ __launch_bounds__(256, 5) void conv_kernel(const float* __restrict__ in,
                                                      const float* __restrict__ bias,
                                                      float* __restrict__ out) {
    int y   = blockIdx.x;
    int b   = blockIdx.y;
    int tid = threadIdx.x;
    int cg  = tid & 15;
    int rg  = tid >> 4;

    // Static schedule entry -> (cout, nchunks, chunk, partial slot, plane base)
    int co, nck, ch, pslot, pbase;
    if      (y < 16) { co = 0;      nck = 16; ch = y;      pslot = y; pbase = 0;  }
    else if (y < 24) { co = 1;      nck = 8;  ch = y - 16; pslot = y; pbase = 16; }
    else if (y < 28) { co = 2;      nck = 4;  ch = y - 24; pslot = y; pbase = 24; }
    else if (y < 30) { co = 3;      nck = 2;  ch = y - 28; pslot = y; pbase = 28; }
    else if (y < 32) { co = 4;      nck = 2;  ch = y - 30; pslot = y; pbase = 30; }
    else             { co = y - 27; nck = 1;  ch = 0;      pslot = -1; pbase = 0; }

    int cnt = g_count[co];
    int lo  = ch * cnt / nck;
    int n   = (ch + 1) * cnt / nck - lo;
    int cobase = co * CH;

    extern __shared__ __align__(16) float smem[];   // [NBUF][TROWS][ROWF]
    uint32_t smem_u32 = (uint32_t)__cvta_generic_to_shared(smem);

    float acc[4][4] = {};

    if (n > 0) {
        // 1056 16B copies per tile: i = 0..3 all threads; i = 4 for tid < 32.
        auto issue = [&](int s) {
            const float* plane = in + (((size_t)b * CH + g_cin[cobase + lo + s]) << 12);
            uint32_t bo = (uint32_t)(s & 1) * BUFB;
            #pragma unroll
            for (int i = 0; i < 5; i++) {
                int idx = tid + 256 * i;
                if (i < 4 || tid < 32) {
                    int r = idx >> 4, c4 = idx & 15;
                    int gy = r - 1;
                    int sz = (gy >= 0 && gy < HH) ? 16 : 0;
                    cp_async16(smem_u32 + bo + (uint32_t)((r * ROWF + 4 * c4) * 4),
                               plane + gy * WW + c4 * 4, sz);
                }
            }
            cp_commit();
        };

        issue(0);

        for (int s = 0; s < n; ++s) {
            cp_wait<0>();
            __syncthreads();              // slot s visible; other buffer free

            if (s + 1 < n) issue(s + 1);

            const float4* wp = reinterpret_cast<const float4*>(g_w + (size_t)(cobase + lo + s) * 12);
            float4 w0 = __ldg(wp);
            float4 w1 = __ldg(wp + 1);
            float4 w2 = __ldg(wp + 2);
            float wk[9] = {w0.x, w0.y, w0.z, w0.w, w1.x, w1.y, w1.z, w1.w, w2.x};

            const float* tb = smem + (s & 1) * BUFF;
            #pragma unroll
            for (int r = 0; r < 6; r++) {
                float4 m = *reinterpret_cast<const float4*>(tb + (4 * rg + r) * ROWF + 4 * cg);
                float lft = __shfl_up_sync(0xffffffffu, m.w, 1);   // lane-1's x = 4cg-1
                float rgt = __shfl_down_sync(0xffffffffu, m.x, 1); // lane+1's x = 4cg+4
                if (cg == 0)  lft = 0.0f;   // image left border
                if (cg == 15) rgt = 0.0f;   // image right border
                float vv[6] = {lft, m.x, m.y, m.z, m.w, rgt};
                #pragma unroll
                for (int dy = 0; dy < 3; dy++) {
                    int orow = r - dy;
                    if (orow >= 0 && orow < 4) {
                        #pragma unroll
                        for (int c = 0; c < 4; c++) {
                            acc[orow][c] = fmaf(wk[dy * 3 + 0], vv[c + 0], acc[orow][c]);
                            acc[orow][c] = fmaf(wk[dy * 3 + 1], vv[c + 1], acc[orow][c]);
                            acc[orow][c] = fmaf(wk[dy * 3 + 2], vv[c + 2], acc[orow][c]);
                        }
                    }
                }
            }
        }
    }

    if (pslot < 0) {
        // Whole cout: write final output with bias.
        float bv = __ldg(bias + co);
        float4* o4 = reinterpret_cast<float4*>(out) + (((size_t)b * CH + co) << 10);
        #pragma unroll
        for (int r = 0; r < 4; r++) {
            int py = 4 * rg + r;
            o4[(py << 4) + cg] =
                make_float4(acc[r][0] + bv, acc[r][1] + bv, acc[r][2] + bv, acc[r][3] + bv);
        }
        return;
    }

    // --- Split cout: write partial plane, then last-arriving block reduces ---
    float4* p4 = reinterpret_cast<float4*>(g_part) + ((size_t)pslot * BATCH + b) * 1024;
    #pragma unroll
    for (int r = 0; r < 4; r++) {
        int py = 4 * rg + r;
        p4[(py << 4) + cg] = make_float4(acc[r][0], acc[r][1], acc[r][2], acc[r][3]);
    }

    __threadfence();                      // make this thread's partials visible
    __syncthreads();                      // all threads' fences done
    __shared__ int s_last;
    if (tid == 0)
        s_last = (atomicAdd(&g_cnt[co * BATCH + b], 1) == nck - 1);
    __syncthreads();

    if (s_last) {
        __threadfence();                  // acquire: see all producers' partials
        float bv = __ldg(bias + co);
        const float4* part4 = reinterpret_cast<const float4*>(g_part);
        float4* o4 = reinterpret_cast<float4*>(out) + (((size_t)b * CH + co) << 10);
        const size_t stride = (size_t)BATCH * 1024;   // one pslot plane (float4)
        size_t base0 = ((size_t)pbase * BATCH + b) * 1024;
        #pragma unroll
        for (int j = 0; j < 4; j++) {
            int v4 = tid + 256 * j;
            float4 accr = make_float4(bv, bv, bv, bv);
            #pragma unroll
            for (int k = 0; k < 16; ++k) {            // fixed k-order: deterministic
                if (k < nck) {
                    float4 p = part4[base0 + (size_t)k * stride + v4];
                    accr.x += p.x; accr.y += p.y; accr.z += p.z; accr.w += p.w;
                }
            }
            o4[v4] = accr;
        }
    }
}

// ---------------------------------------------------------------------------
// Entry point. Inputs (metadata order): input, conv_w, conv_b, weight.
// Two launches total: prep (cumprod+compact+counter reset) and conv (with
// embedded deterministic reduction).  Graph-capturable, allocation-free.
// ---------------------------------------------------------------------------
extern "C" void kernel_launch(void* const* d_in, const int* in_sizes, int n_in,
                              void* d_out, int out_size) {
    (void)in_sizes; (void)n_in; (void)out_size;
    const float* input  = (const float*)d_in[0];
    const float* conv_w = (const float*)d_in[1];
    const float* conv_b = (const float*)d_in[2];
    const float* weight = (const float*)d_in[3];
    float* out = (float*)d_out;

    const int dyn_smem = NBUF * BUFB;   // 35904 bytes
    cudaFuncSetAttribute(conv_kernel, cudaFuncAttributeMaxDynamicSharedMemorySize, dyn_smem);

    prep_kernel<<<CH, CH>>>(weight, conv_w);
    dim3 grid(GRID_X, BATCH);
    conv_kernel<<<grid, 256, dyn_smem>>>(input, conv_b, out);
}

// round 14
// speedup vs baseline: 1.1957x; 1.1957x over previous
#include <cuda_runtime.h>
#include <cstdint>

// Problem constants
#define BATCH 16
#define CH    256
#define HH    64
#define WW    64
#define ROWF  68                   // smem row stride in floats
#define WROWS 10                   // input rows per warp strip (8 + 2 halo)
#define WBUF  (WROWS * ROWF)       // 680 floats per warp buffer
#define NBUF  2
#define WSTRIDE (NBUF * WBUF)      // floats per warp region (1360)
#define DYN_SMEM (8 * WSTRIDE * 4) // 43520 bytes

// Split schedule: co0->16, co1->8, co2->4, co3->2, co4->2 chunks, rest->1.
#define NSPLIT 32
#define GRID_X (NSPLIT + 251)      // 283 schedule entries

// ---------------------------------------------------------------------------
// Scratch (device globals — no runtime allocation allowed)
// ---------------------------------------------------------------------------
__device__ int   g_cin  [CH * CH];
__device__ float g_w    [CH * CH * 12];
__device__ int   g_count[CH];
__device__ float g_part [NSPLIT * BATCH * HH * WW];   // 8 MB partials

// ---------------------------------------------------------------------------
// cp.async helpers
// ---------------------------------------------------------------------------
__device__ __forceinline__ void cp_async16(uint32_t saddr, const float* gptr, int src_size) {
    asm volatile("cp.async.ca.shared.global [%0], [%1], 16, %2;\n"
                 :: "r"(saddr), "l"(gptr), "r"(src_size));
}
__device__ __forceinline__ void cp_commit() {
    asm volatile("cp.async.commit_group;\n" ::);
}
template <int N> __device__ __forceinline__ void cp_wait() {
    asm volatile("cp.async.wait_group %0;\n" :: "n"(N));
}

// ---------------------------------------------------------------------------
// K1: fused cumprod + compaction.  Block = cout (256), thread = cin (256).
// Serial register cumprod with uniform early-exit once the column is all
// zero, then deterministic ballot/popc compaction + scale-folded weights.
// ---------------------------------------------------------------------------
__global__ void prep_kernel(const float* __restrict__ weight,
                            const float* __restrict__ conv_w) {
    int co  = blockIdx.x;
    int cin = threadIdx.x;

    float sc = 1.0f;
    for (int j = 1; j <= co; ++j) {
        sc *= fmaxf(weight[j * CH + cin], 0.0f);
        if ((j & 7) == 0) {
            if (__syncthreads_count(sc != 0.0f) == 0) break;   // uniform exit
        }
    }

    bool active = (sc != 0.0f);
    unsigned mask = __ballot_sync(0xffffffffu, active);
    int lane = cin & 31, warp = cin >> 5;
    __shared__ int wcnt[8];
    if (lane == 0) wcnt[warp] = __popc(mask);
    __syncthreads();
    int base = 0;
    #pragma unroll
    for (int i = 0; i < 8; i++)
        if (i < warp) base += wcnt[i];
    if (active) {
        int slot = base + __popc(mask & ((1u << lane) - 1u));
        g_cin[co * CH + slot] = cin;
        const float* ws = conv_w + (size_t)(co * CH + cin) * 9;
        float*       wd = g_w    + (size_t)(co * CH + slot) * 12;
        #pragma unroll
        for (int k = 0; k < 9; k++) wd[k] = ws[k] * sc;
        wd[9] = 0.0f; wd[10] = 0.0f; wd[11] = 0.0f;
    }
    if (cin == 0) {
        int t = 0;
        #pragma unroll
        for (int i = 0; i < 8; i++) t += wcnt[i];
        g_count[co] = t;
    }
}

// ---------------------------------------------------------------------------
// K2: barrier-free whole-plane 3x3 conv.  grid = (283 entries, 16 batch),
// 256 threads.  Each warp owns output rows 8w..8w+7 and streams its own
// 10-row input strip (rows 8w-1..8w+8) through a warp-private 2-buffer
// cp.async ring — no __syncthreads anywhere; warps pipeline independently.
// Inner loop identical to the champion: LDS.128 + 2 shuffles per row.
// ---------------------------------------------------------------------------
__global__ __launch_bounds__(256, 4) void conv_kernel(const float* __restrict__ in,
                                                      const float* __restrict__ bias,
                                                      float* __restrict__ out) {
    int y    = blockIdx.x;
    int b    = blockIdx.y;
    int tid  = threadIdx.x;
    int lane = tid & 31;
    int w    = tid >> 5;
    int cg   = tid & 15;
    int rgp  = (tid >> 4) & 1;      // warp-local row group (0/1)

    // Static schedule entry -> (cout, nchunks, chunk, partial slot)
    int co, nck, ch, pslot;
    if      (y < 16) { co = 0;      nck = 16; ch = y;      pslot = y;  }
    else if (y < 24) { co = 1;      nck = 8;  ch = y - 16; pslot = y;  }
    else if (y < 28) { co = 2;      nck = 4;  ch = y - 24; pslot = y;  }
    else if (y < 30) { co = 3;      nck = 2;  ch = y - 28; pslot = y;  }
    else if (y < 32) { co = 4;      nck = 2;  ch = y - 30; pslot = y;  }
    else             { co = y - 27; nck = 1;  ch = 0;      pslot = -1; }

    int cnt = g_count[co];
    int lo  = ch * cnt / nck;
    int n   = (ch + 1) * cnt / nck - lo;
    int cobase = co * CH;

    extern __shared__ __align__(16) float smem[];
    float* wt = smem + w * WSTRIDE;                 // this warp's region
    uint32_t wt_u32 = (uint32_t)__cvta_generic_to_shared(wt);

    // Per-lane copy descriptors: 160 16B chunks per strip, 5 per lane.
    // Chunk c = lane + 32*i -> smem row r = c>>4, col group c4 = c&15,
    // input row gy = 8w - 1 + r (out-of-image rows zero-filled via sz=0).
    uint32_t so[5]; int go[5]; int sz[5];
    #pragma unroll
    for (int i = 0; i < 5; i++) {
        int c  = lane + 32 * i;
        int r  = c >> 4, c4 = c & 15;
        int gy = 8 * w - 1 + r;
        sz[i]  = (gy >= 0 && gy < HH) ? 16 : 0;
        go[i]  = gy * WW + 4 * c4;
        so[i]  = wt_u32 + (uint32_t)((r * ROWF + 4 * c4) * 4);
    }

    float acc[4][4] = {};

    if (n > 0) {
        auto issue = [&](int s) {
            const float* plane = in + (((size_t)b * CH + g_cin[cobase + lo + s]) << 12);
            uint32_t bo = (uint32_t)(s & 1) * (WBUF * 4);
            #pragma unroll
            for (int i = 0; i < 5; i++) cp_async16(so[i] + bo, plane + go[i], sz[i]);
            cp_commit();
        };

        issue(0);

        for (int s = 0; s < n; ++s) {
            __syncwarp();                 // prior compute done before refill
            if (s + 1 < n) { issue(s + 1); cp_wait<1>(); }
            else           { cp_wait<0>(); }
            __syncwarp();                 // slot s visible to all lanes

            const float4* wp = reinterpret_cast<const float4*>(g_w + (size_t)(cobase + lo + s) * 12);
            float4 w0 = __ldg(wp);
            float4 w1 = __ldg(wp + 1);
            float4 w2 = __ldg(wp + 2);
            float wk[9] = {w0.x, w0.y, w0.z, w0.w, w1.x, w1.y, w1.z, w1.w, w2.x};

            const float* tb = wt + (s & 1) * WBUF;
            #pragma unroll
            for (int r = 0; r < 6; r++) {
                float4 m = *reinterpret_cast<const float4*>(tb + (4 * rgp + r) * ROWF + 4 * cg);
                float lft = __shfl_up_sync(0xffffffffu, m.w, 1);   // lane-1's x = 4cg-1
                float rgt = __shfl_down_sync(0xffffffffu, m.x, 1); // lane+1's x = 4cg+4
                if (cg == 0)  lft = 0.0f;   // image left border
                if (cg == 15) rgt = 0.0f;   // image right border
                float vv[6] = {lft, m.x, m.y, m.z, m.w, rgt};
                #pragma unroll
                for (int dy = 0; dy < 3; dy++) {
                    int orow = r - dy;
                    if (orow >= 0 && orow < 4) {
                        #pragma unroll
                        for (int c = 0; c < 4; c++) {
                            acc[orow][c] = fmaf(wk[dy * 3 + 0], vv[c + 0], acc[orow][c]);
                            acc[orow][c] = fmaf(wk[dy * 3 + 1], vv[c + 1], acc[orow][c]);
                            acc[orow][c] = fmaf(wk[dy * 3 + 2], vv[c + 2], acc[orow][c]);
                        }
                    }
                }
            }
        }
    }

    int rg = tid >> 4;                    // global row group 0..15 (= 2w + rgp)
    if (pslot < 0) {
        float bv = __ldg(bias + co);
        float4* o4 = reinterpret_cast<float4*>(out) + (((size_t)b * CH + co) << 10);
        #pragma unroll
        for (int r = 0; r < 4; r++) {
            int py = 4 * rg + r;
            o4[(py << 4) + cg] =
                make_float4(acc[r][0] + bv, acc[r][1] + bv, acc[r][2] + bv, acc[r][3] + bv);
        }
    } else {
        // Unconditional partial write (replay-safe even when n == 0).
        float4* p4 = reinterpret_cast<float4*>(g_part) + ((size_t)pslot * BATCH + b) * 1024;
        #pragma unroll
        for (int r = 0; r < 4; r++) {
            int py = 4 * rg + r;
            p4[(py << 4) + cg] = make_float4(acc[r][0], acc[r][1], acc[r][2], acc[r][3]);
        }
    }
}

// ---------------------------------------------------------------------------
// K3: reduce partials for the 5 split couts, add bias (champion version).
// grid = 5*16*4 = 320 blocks, 256 threads, 1 float4/thread, unrolled guarded
// 16-deep k-loop (MLP up to 16).
// ---------------------------------------------------------------------------
__global__ __launch_bounds__(256) void reduce_kernel(const float* __restrict__ bias,
                                                     float* __restrict__ out) {
    const int nck_t[5]   = {16, 8, 4, 2, 2};
    const int pbase_t[5] = {0, 16, 24, 28, 30};
    int blk = blockIdx.x;
    int co  = blk >> 6;            // 0..4
    int rem = blk & 63;
    int b   = rem >> 2;            // 0..15
    int q   = rem & 3;             // px chunk
    int nck = nck_t[co], pbase = pbase_t[co];

    int v4 = q * 256 + threadIdx.x;          // 0..1023 float4 index
    float bv = __ldg(bias + co);
    float4 acc = make_float4(bv, bv, bv, bv);

    const float4* part4 = reinterpret_cast<const float4*>(g_part);
    size_t base = ((size_t)pbase * BATCH + b) * 1024 + v4;
    const size_t stride = (size_t)BATCH * 1024;

    #pragma unroll
    for (int k = 0; k < 16; ++k) {
        if (k < nck) {
            float4 p = part4[base + (size_t)k * stride];
            acc.x += p.x; acc.y += p.y; acc.z += p.z; acc.w += p.w;
        }
    }

    reinterpret_cast<float4*>(out)[(((size_t)b * CH + co) << 10) + v4] = acc;
}

// ---------------------------------------------------------------------------
// Entry point. Inputs (metadata order): input, conv_w, conv_b, weight.
// Three launches: prep (fused scan+compact), conv (barrier-free), reduce.
// Graph-capturable, allocation-free, deterministic.
// ---------------------------------------------------------------------------
extern "C" void kernel_launch(void* const* d_in, const int* in_sizes, int n_in,
                              void* d_out, int out_size) {
    (void)in_sizes; (void)n_in; (void)out_size;
    const float* input  = (const float*)d_in[0];
    const float* conv_w = (const float*)d_in[1];
    const float* conv_b = (const float*)d_in[2];
    const float* weight = (const float*)d_in[3];
    float* out = (float*)d_out;

    cudaFuncSetAttribute(conv_kernel, cudaFuncAttributeMaxDynamicSharedMemorySize, DYN_SMEM);

    prep_kernel<<<CH, CH>>>(weight, conv_w);
    dim3 grid(GRID_X, BATCH);
    conv_kernel<<<grid, 256, DYN_SMEM>>>(input, conv_b, out);
    reduce_kernel<<<5 * BATCH * 4, 256>>>(conv_b, out);
}

// round 16
// speedup vs baseline: 1.2782x; 1.0689x over previous
#include <cuda_runtime.h>
#include <cstdint>

// Problem constants
#define BATCH 16
#define CH    256
#define HH    64
#define WW    64
#define ROWF  68                   // smem row stride in floats
#define WROWS 10                   // input rows per warp strip (8 + 2 halo)
#define WBUF  (WROWS * ROWF)       // 680 floats per warp buffer
#define NBUF  2
#define WSTRIDE (NBUF * WBUF)      // floats per warp region (1360)
#define DYN_SMEM (8 * WSTRIDE * 4) // 43520 bytes

// Split schedule: co0->16, co1->8, co2->4, co3->2, co4->2 chunks, rest->1.
#define NSPLIT 32
#define GRID_X (NSPLIT + 251)      // 283 schedule entries

// ---------------------------------------------------------------------------
// Scratch (device globals — no runtime allocation allowed)
// ---------------------------------------------------------------------------
__device__ float g_scale[CH * CH];
__device__ int   g_cin  [CH * CH];
__device__ float g_w    [CH * CH * 12];
__device__ int   g_count[CH];
__device__ float g_part [NSPLIT * BATCH * HH * WW];   // 8 MB partials

// ---------------------------------------------------------------------------
// cp.async helpers
// ---------------------------------------------------------------------------
__device__ __forceinline__ void cp_async16(uint32_t saddr, const float* gptr, int src_size) {
    asm volatile("cp.async.ca.shared.global [%0], [%1], 16, %2;\n"
                 :: "r"(saddr), "l"(gptr), "r"(src_size));
}
__device__ __forceinline__ void cp_commit() {
    asm volatile("cp.async.commit_group;\n" ::);
}
template <int N> __device__ __forceinline__ void cp_wait() {
    asm volatile("cp.async.wait_group %0;\n" :: "n"(N));
}

// ---------------------------------------------------------------------------
// K1a: parallel cumprod (Kogge-Stone, 8 steps). Block = cin, thread = cout.
// ---------------------------------------------------------------------------
__global__ void scan_kernel(const float* __restrict__ weight) {
    int cin = blockIdx.x;
    int co  = threadIdx.x;
    __shared__ float sh[CH];
    sh[co] = (co == 0) ? 1.0f : fmaxf(weight[co * CH + cin], 0.0f);
    __syncthreads();
    #pragma unroll
    for (int off = 1; off < CH; off <<= 1) {
        float t = (co >= off) ? sh[co - off] : 1.0f;
        __syncthreads();
        sh[co] *= t;
        __syncthreads();
    }
    g_scale[co * CH + cin] = sh[co];
}

// ---------------------------------------------------------------------------
// K1b: deterministic per-cout compaction (ballot + popc prefix, no atomics).
// ---------------------------------------------------------------------------
__global__ void compact_kernel(const float* __restrict__ conv_w) {
    int co  = blockIdx.x;
    int cin = threadIdx.x;
    float sc = g_scale[co * CH + cin];
    bool active = (sc != 0.0f);
    unsigned mask = __ballot_sync(0xffffffffu, active);
    int lane = cin & 31, warp = cin >> 5;
    __shared__ int wcnt[8];
    if (lane == 0) wcnt[warp] = __popc(mask);
    __syncthreads();
    int base = 0;
    #pragma unroll
    for (int i = 0; i < 8; i++)
        if (i < warp) base += wcnt[i];
    if (active) {
        int slot = base + __popc(mask & ((1u << lane) - 1u));
        g_cin[co * CH + slot] = cin;
        const float* ws = conv_w + (size_t)(co * CH + cin) * 9;
        float*       wd = g_w    + (size_t)(co * CH + slot) * 12;
        #pragma unroll
        for (int k = 0; k < 9; k++) wd[k] = ws[k] * sc;
        wd[9] = 0.0f; wd[10] = 0.0f; wd[11] = 0.0f;
    }
    if (cin == 0) {
        int t = 0;
        #pragma unroll
        for (int i = 0; i < 8; i++) t += wcnt[i];
        g_count[co] = t;
    }
}

// ---------------------------------------------------------------------------
// K2: barrier-free whole-plane 3x3 conv (unchanged champion).
// grid = (283 entries, 16 batch), 256 threads.  Each warp owns output rows
// 8w..8w+7 and streams its own 10-row input strip (rows 8w-1..8w+8) through
// a warp-private 2-buffer cp.async ring — no __syncthreads; warps pipeline
// independently.  Inner loop: LDS.128 + 2 shuffles per row.
// ---------------------------------------------------------------------------
__global__ __launch_bounds__(256, 4) void conv_kernel(const float* __restrict__ in,
                                                      const float* __restrict__ bias,
                                                      float* __restrict__ out) {
    int y    = blockIdx.x;
    int b    = blockIdx.y;
    int tid  = threadIdx.x;
    int lane = tid & 31;
    int w    = tid >> 5;
    int cg   = tid & 15;
    int rgp  = (tid >> 4) & 1;      // warp-local row group (0/1)

    // Static schedule entry -> (cout, nchunks, chunk, partial slot)
    int co, nck, ch, pslot;
    if      (y < 16) { co = 0;      nck = 16; ch = y;      pslot = y;  }
    else if (y < 24) { co = 1;      nck = 8;  ch = y - 16; pslot = y;  }
    else if (y < 28) { co = 2;      nck = 4;  ch = y - 24; pslot = y;  }
    else if (y < 30) { co = 3;      nck = 2;  ch = y - 28; pslot = y;  }
    else if (y < 32) { co = 4;      nck = 2;  ch = y - 30; pslot = y;  }
    else             { co = y - 27; nck = 1;  ch = 0;      pslot = -1; }

    int cnt = g_count[co];
    int lo  = ch * cnt / nck;
    int n   = (ch + 1) * cnt / nck - lo;
    int cobase = co * CH;

    extern __shared__ __align__(16) float smem[];
    float* wt = smem + w * WSTRIDE;                 // this warp's region
    uint32_t wt_u32 = (uint32_t)__cvta_generic_to_shared(wt);

    // Per-lane copy descriptors: 160 16B chunks per strip, 5 per lane.
    uint32_t so[5]; int go[5]; int sz[5];
    #pragma unroll
    for (int i = 0; i < 5; i++) {
        int c  = lane + 32 * i;
        int r  = c >> 4, c4 = c & 15;
        int gy = 8 * w - 1 + r;
        sz[i]  = (gy >= 0 && gy < HH) ? 16 : 0;
        go[i]  = gy * WW + 4 * c4;
        so[i]  = wt_u32 + (uint32_t)((r * ROWF + 4 * c4) * 4);
    }

    float acc[4][4] = {};

    if (n > 0) {
        auto issue = [&](int s) {
            const float* plane = in + (((size_t)b * CH + g_cin[cobase + lo + s]) << 12);
            uint32_t bo = (uint32_t)(s & 1) * (WBUF * 4);
            #pragma unroll
            for (int i = 0; i < 5; i++) cp_async16(so[i] + bo, plane + go[i], sz[i]);
            cp_commit();
        };

        issue(0);

        for (int s = 0; s < n; ++s) {
            __syncwarp();                 // prior compute done before refill
            if (s + 1 < n) { issue(s + 1); cp_wait<1>(); }
            else           { cp_wait<0>(); }
            __syncwarp();                 // slot s visible to all lanes

            const float4* wp = reinterpret_cast<const float4*>(g_w + (size_t)(cobase + lo + s) * 12);
            float4 w0 = __ldg(wp);
            float4 w1 = __ldg(wp + 1);
            float4 w2 = __ldg(wp + 2);
            float wk[9] = {w0.x, w0.y, w0.z, w0.w, w1.x, w1.y, w1.z, w1.w, w2.x};

            const float* tb = wt + (s & 1) * WBUF;
            #pragma unroll
            for (int r = 0; r < 6; r++) {
                float4 m = *reinterpret_cast<const float4*>(tb + (4 * rgp + r) * ROWF + 4 * cg);
                float lft = __shfl_up_sync(0xffffffffu, m.w, 1);   // lane-1's x = 4cg-1
                float rgt = __shfl_down_sync(0xffffffffu, m.x, 1); // lane+1's x = 4cg+4
                if (cg == 0)  lft = 0.0f;   // image left border
                if (cg == 15) rgt = 0.0f;   // image right border
                float vv[6] = {lft, m.x, m.y, m.z, m.w, rgt};
                #pragma unroll
                for (int dy = 0; dy < 3; dy++) {
                    int orow = r - dy;
                    if (orow >= 0 && orow < 4) {
                        #pragma unroll
                        for (int c = 0; c < 4; c++) {
                            acc[orow][c] = fmaf(wk[dy * 3 + 0], vv[c + 0], acc[orow][c]);
                            acc[orow][c] = fmaf(wk[dy * 3 + 1], vv[c + 1], acc[orow][c]);
                            acc[orow][c] = fmaf(wk[dy * 3 + 2], vv[c + 2], acc[orow][c]);
                        }
                    }
                }
            }
        }
    }

    int rg = tid >> 4;                    // global row group 0..15 (= 2w + rgp)
    if (pslot < 0) {
        float bv = __ldg(bias + co);
        float4* o4 = reinterpret_cast<float4*>(out) + (((size_t)b * CH + co) << 10);
        #pragma unroll
        for (int r = 0; r < 4; r++) {
            int py = 4 * rg + r;
            o4[(py << 4) + cg] =
                make_float4(acc[r][0] + bv, acc[r][1] + bv, acc[r][2] + bv, acc[r][3] + bv);
        }
    } else {
        // Unconditional partial write (replay-safe even when n == 0).
        float4* p4 = reinterpret_cast<float4*>(g_part) + ((size_t)pslot * BATCH + b) * 1024;
        #pragma unroll
        for (int r = 0; r < 4; r++) {
            int py = 4 * rg + r;
            p4[(py << 4) + cg] = make_float4(acc[r][0], acc[r][1], acc[r][2], acc[r][3]);
        }
    }
}

// ---------------------------------------------------------------------------
// K3: reduce partials for the 5 split couts, add bias (champion version).
// grid = 5*16*4 = 320 blocks, 256 threads, 1 float4/thread, unrolled guarded
// 16-deep k-loop (MLP up to 16).
// ---------------------------------------------------------------------------
__global__ __launch_bounds__(256) void reduce_kernel(const float* __restrict__ bias,
                                                     float* __restrict__ out) {
    const int nck_t[5]   = {16, 8, 4, 2, 2};
    const int pbase_t[5] = {0, 16, 24, 28, 30};
    int blk = blockIdx.x;
    int co  = blk >> 6;            // 0..4
    int rem = blk & 63;
    int b   = rem >> 2;            // 0..15
    int q   = rem & 3;             // px chunk
    int nck = nck_t[co], pbase = pbase_t[co];

    int v4 = q * 256 + threadIdx.x;          // 0..1023 float4 index
    float bv = __ldg(bias + co);
    float4 acc = make_float4(bv, bv, bv, bv);

    const float4* part4 = reinterpret_cast<const float4*>(g_part);
    size_t base = ((size_t)pbase * BATCH + b) * 1024 + v4;
    const size_t stride = (size_t)BATCH * 1024;

    #pragma unroll
    for (int k = 0; k < 16; ++k) {
        if (k < nck) {
            float4 p = part4[base + (size_t)k * stride];
            acc.x += p.x; acc.y += p.y; acc.z += p.z; acc.w += p.w;
        }
    }

    reinterpret_cast<float4*>(out)[(((size_t)b * CH + co) << 10) + v4] = acc;
}

// ---------------------------------------------------------------------------
// Entry point. Inputs (metadata order): input, conv_w, conv_b, weight.
// Four launches: Kogge-Stone scan, compact, barrier-free conv, reduce.
// Graph-capturable, allocation-free, deterministic.
// ---------------------------------------------------------------------------
extern "C" void kernel_launch(void* const* d_in, const int* in_sizes, int n_in,
                              void* d_out, int out_size) {
    (void)in_sizes; (void)n_in; (void)out_size;
    const float* input  = (const float*)d_in[0];
    const float* conv_w = (const float*)d_in[1];
    const float* conv_b = (const float*)d_in[2];
    const float* weight = (const float*)d_in[3];
    float* out = (float*)d_out;

    cudaFuncSetAttribute(conv_kernel, cudaFuncAttributeMaxDynamicSharedMemorySize, DYN_SMEM);

    scan_kernel<<<CH, CH>>>(weight);
    compact_kernel<<<CH, CH>>>(conv_w);
    dim3 grid(GRID_X, BATCH);
    conv_kernel<<<grid, 256, DYN_SMEM>>>(input, conv_b, out);
    reduce_kernel<<<5 * BATCH * 4, 256>>>(conv_b, out);
}